// round 6
// baseline (speedup 1.0000x reference)
#include <cuda_runtime.h>
#include <stdint.h>

#define BATCH   64
#define SEQ     512
#define EMBD    768
#define DM      32
#define NH      4
#define NCQ     16
#define NCODES  8192
#define NSAMP   16
#define NROWS   (BATCH * NCQ)      /* 1024 */
#define NTOK    (BATCH * SEQ)      /* 32768 */

typedef unsigned long long u64;

/* ------------------------------------------------------------------ */
/* scratch (static device memory; no allocations anywhere)            */
/* ------------------------------------------------------------------ */
__device__ float g_x[NTOK * DM];
__device__ float g_qkv[NTOK * 96];
__device__ float g_ao[NTOK * DM];
__device__ float g_xc[NROWS * EMBD];
__device__ float g_xn2[NROWS];
__device__ float g_cn2[NCODES];
__device__ float g_logit[(size_t)NROWS * NCODES];
__device__ int   g_cand[(size_t)NROWS * 64];
__device__ int   g_candcnt[NROWS];
__device__ float g_thr[NROWS];
__device__ int   g_draw[NSAMP * NROWS];

/* transposed weights: Wt[k][out] for broadcast-friendly access */
__device__ float gWt_fcin[768 * 32];
__device__ float gWt_qkv[2 * 32 * 96];
__device__ float gWt_out[2 * 32 * 32];
__device__ float gWt_ff1[2 * 32 * 64];
__device__ float gWt_ff2[2 * 64 * 32];

/* ------------------------------------------------------------------ */
/* packed f32x2 helpers (Blackwell FFMA2 — bit-exact 2x fp32 FMA)      */
/* ------------------------------------------------------------------ */
__device__ __forceinline__ u64 dup2(float a) {
    u64 d;
    asm("mov.b64 %0, {%1, %1};" : "=l"(d) : "r"(__float_as_uint(a)));
    return d;
}
__device__ __forceinline__ u64 pk2(float lo, float hi) {
    u64 d;
    asm("mov.b64 %0, {%1, %2};" : "=l"(d)
        : "r"(__float_as_uint(lo)), "r"(__float_as_uint(hi)));
    return d;
}
__device__ __forceinline__ void fma2(u64& d, u64 a, u64 b) {
    asm("fma.rn.f32x2 %0, %1, %2, %0;" : "+l"(d) : "l"(a), "l"(b));
}
__device__ __forceinline__ float2 unpk(u64 d) {
    uint32_t lo, hi;
    asm("mov.b64 {%0, %1}, %2;" : "=r"(lo), "=r"(hi) : "l"(d));
    return make_float2(__uint_as_float(lo), __uint_as_float(hi));
}

/* acc2[16] += xk * wrow[0..31]  (16 packed pairs) */
__device__ __forceinline__ void mat32_f32x2(u64 (&acc2)[16], float xk,
                                            const float* wrow) {
    u64 x2 = dup2(xk);
    const ulonglong2* w2 = (const ulonglong2*)wrow;
#pragma unroll
    for (int p = 0; p < 8; p++) {
        ulonglong2 q = w2[p];
        fma2(acc2[p * 2 + 0], x2, q.x);
        fma2(acc2[p * 2 + 1], x2, q.y);
    }
}

/* ------------------------------------------------------------------ */
/* PRNG: jax threefry2x32, key (0,42), partitionable scheme            */
/* ------------------------------------------------------------------ */
__device__ __forceinline__ void threefry_0_42(uint32_t c0, uint32_t c1,
                                              uint32_t& o0, uint32_t& o1) {
    const uint32_t k0 = 0u, k1 = 42u, k2 = 0x1BD11BDAu ^ k0 ^ k1;
    uint32_t x0 = c0 + k0, x1 = c1 + k1;
#define TF_RND(r) { x0 += x1; x1 = __funnelshift_l(x1, x1, r); x1 ^= x0; }
    TF_RND(13) TF_RND(15) TF_RND(26) TF_RND(6)
    x0 += k1; x1 += k2 + 1u;
    TF_RND(17) TF_RND(29) TF_RND(16) TF_RND(24)
    x0 += k2; x1 += k0 + 2u;
    TF_RND(13) TF_RND(15) TF_RND(26) TF_RND(6)
    x0 += k0; x1 += k1 + 3u;
    TF_RND(17) TF_RND(29) TF_RND(16) TF_RND(24)
    x0 += k1; x1 += k2 + 4u;
    TF_RND(13) TF_RND(15) TF_RND(26) TF_RND(6)
    x0 += k2; x1 += k0 + 5u;
#undef TF_RND
    o0 = x0; o1 = x1;
}
__device__ __forceinline__ float gumbel_idx(uint32_t i) {
    uint32_t o0, o1;
    threefry_0_42(0u, i, o0, o1);
    uint32_t bits = o0 ^ o1;
    float f = __uint_as_float((bits >> 9) | 0x3f800000u) - 1.0f;
    float u = fmaxf(f, 1.17549435e-38f);
    return -logf(-logf(u));
}

/* ------------------------------------------------------------------ */
/* 0. weight transposes (tiny, once per launch)                        */
/* ------------------------------------------------------------------ */
__global__ void __launch_bounds__(256) k_prep(
        const float* __restrict__ fcinw, const float* __restrict__ encinw,
        const float* __restrict__ encow, const float* __restrict__ ff1w,
        const float* __restrict__ ff2w) {
    int i = blockIdx.x * 256 + threadIdx.x;
    if (i < 24576) { int k = i >> 5, c = i & 31; gWt_fcin[i] = fcinw[c * 768 + k]; return; }
    int j = i - 24576;
    if (j < 6144) { int l = j / 3072, r = j % 3072; int k = r / 96, q = r % 96;
        gWt_qkv[j] = encinw[l * 3072 + q * 32 + k]; return; }
    j -= 6144;
    if (j < 2048) { int l = j / 1024, r = j % 1024; int k = r >> 5, c = r & 31;
        gWt_out[j] = encow[l * 1024 + c * 32 + k]; return; }
    j -= 2048;
    if (j < 4096) { int l = j / 2048, r = j % 2048; int k = r / 64, c = r % 64;
        gWt_ff1[j] = ff1w[l * 2048 + c * 32 + k]; return; }
    j -= 4096;
    if (j < 4096) { int l = j / 2048, r = j % 2048; int k = r >> 5, c = r & 31;
        gWt_ff2[j] = ff2w[l * 2048 + c * 64 + k]; }
}

/* qkv for one token from x regs; weights smem row-major k*96          */
__device__ __forceinline__ void qkv_from_x(const float (&x)[32],
                                           const float* swq,
                                           const float* sbq, float* qo) {
#pragma unroll
    for (int part = 0; part < 3; part++) {
        u64 a2[16];
#pragma unroll
        for (int p = 0; p < 16; p++)
            a2[p] = pk2(sbq[part * 32 + 2 * p], sbq[part * 32 + 2 * p + 1]);
#pragma unroll 4
        for (int k = 0; k < 32; k++)
            mat32_f32x2(a2, x[k], swq + k * 96 + part * 32);
        float4* o4 = (float4*)(qo + part * 32);
#pragma unroll
        for (int p4 = 0; p4 < 8; p4++) {
            float2 va = unpk(a2[p4 * 2]), vb = unpk(a2[p4 * 2 + 1]);
            o4[p4] = make_float4(va.x, va.y, vb.x, vb.y);
        }
    }
}

/* ------------------------------------------------------------------ */
/* 1. fused: x = xcq @ fc_in_w^T + b ; qkv(layer0)                     */
/* ------------------------------------------------------------------ */
__global__ void __launch_bounds__(128) k_fcin(const float* __restrict__ xcq,
                                              const float* __restrict__ bias,
                                              const float* __restrict__ encinb) {
    __shared__ __align__(16) float sx[128 * 33];
    __shared__ __align__(16) float sw[1024];
    __shared__ float sbq[96];
    int tok0 = blockIdx.x * 128;
    int t = threadIdx.x;
    u64 acc2[16];
#pragma unroll
    for (int p = 0; p < 16; p++) acc2[p] = 0ull;
    for (int k0 = 0; k0 < 768; k0 += 32) {
        for (int i = t; i < 4096; i += 128) {
            int tok = i >> 5, k = i & 31;
            sx[tok * 33 + k] = xcq[(size_t)(tok0 + tok) * 768 + k0 + k];
        }
        for (int i = t; i < 1024; i += 128) sw[i] = gWt_fcin[k0 * 32 + i];
        __syncthreads();
#pragma unroll 4
        for (int k = 0; k < 32; k++)
            mat32_f32x2(acc2, sx[t * 33 + k], sw + k * 32);
        __syncthreads();
    }
    float x[32];
#pragma unroll
    for (int p = 0; p < 16; p++) {
        float2 v = unpk(acc2[p]);
        x[2 * p] = v.x + bias[2 * p];
        x[2 * p + 1] = v.y + bias[2 * p + 1];
    }
    {
        float4* xo = (float4*)(g_x + (size_t)(tok0 + t) * 32);
#pragma unroll
        for (int c4 = 0; c4 < 8; c4++)
            xo[c4] = make_float4(x[c4 * 4], x[c4 * 4 + 1], x[c4 * 4 + 2], x[c4 * 4 + 3]);
    }
    __syncthreads();
    for (int i = t; i < 3072; i += 128) sx[i] = gWt_qkv[i];
    if (t < 96) sbq[t] = encinb[t];
    __syncthreads();
    qkv_from_x(x, sx, sbq, g_qkv + (size_t)(tok0 + t) * 96);
}

/* ------------------------------------------------------------------ */
/* 2. attention: thread per query, online softmax                      */
/* ------------------------------------------------------------------ */
__global__ void __launch_bounds__(512) k_attn(const int* __restrict__ amask) {
    __shared__ __align__(16) float Ks[512 * 8];
    __shared__ __align__(16) float Vs[512 * 8];
    __shared__ float vm[512];
    int b = blockIdx.x >> 2, h = blockIdx.x & 3;
    const float* qkvb = g_qkv + (size_t)b * 512 * 96;
    for (int i = threadIdx.x; i < 4096; i += 512) {
        int key = i >> 3, d = i & 7;
        Ks[i] = qkvb[key * 96 + 32 + h * 8 + d];
        Vs[i] = qkvb[key * 96 + 64 + h * 8 + d];
    }
    {
        int key = threadIdx.x;
        vm[key] = (key < NCQ || amask[b * (SEQ - NCQ) + key - NCQ] != 0) ? 1.f : 0.f;
    }
    __syncthreads();
    int q = threadIdx.x;
    float qv[8];
    {
        const float4* qp = (const float4*)(qkvb + q * 96 + h * 8);
        float4 q0 = qp[0], q1 = qp[1];
        qv[0] = q0.x; qv[1] = q0.y; qv[2] = q0.z; qv[3] = q0.w;
        qv[4] = q1.x; qv[5] = q1.y; qv[6] = q1.z; qv[7] = q1.w;
    }
    float m = -3.0e38f, s = 0.f;
    float pv[8];
#pragma unroll
    for (int d = 0; d < 8; d++) pv[d] = 0.f;
    const float4* K4 = (const float4*)Ks;
    const float4* V4 = (const float4*)Vs;
    for (int key = 0; key < 512; key++) {
        if (vm[key] == 0.f) continue;
        float4 ka = K4[key * 2], kb = K4[key * 2 + 1];
        float dot = qv[0] * ka.x + qv[1] * ka.y + qv[2] * ka.z + qv[3] * ka.w
                  + qv[4] * kb.x + qv[5] * kb.y + qv[6] * kb.z + qv[7] * kb.w;
        dot *= 0.35355339059327373f;
        float4 va = V4[key * 2], vb = V4[key * 2 + 1];
        if (dot <= m) {
            float e = expf(dot - m);
            s += e;
            pv[0] += e * va.x; pv[1] += e * va.y; pv[2] += e * va.z; pv[3] += e * va.w;
            pv[4] += e * vb.x; pv[5] += e * vb.y; pv[6] += e * vb.z; pv[7] += e * vb.w;
        } else {
            float r = expf(m - dot);
            s = s * r + 1.f;
            pv[0] = pv[0] * r + va.x; pv[1] = pv[1] * r + va.y;
            pv[2] = pv[2] * r + va.z; pv[3] = pv[3] * r + va.w;
            pv[4] = pv[4] * r + vb.x; pv[5] = pv[5] * r + vb.y;
            pv[6] = pv[6] * r + vb.z; pv[7] = pv[7] * r + vb.w;
            m = dot;
        }
    }
    float inv = 1.f / s;
    float4* o4 = (float4*)(g_ao + ((size_t)(b * 512 + q)) * 32 + h * 8);
    o4[0] = make_float4(pv[0] * inv, pv[1] * inv, pv[2] * inv, pv[3] * inv);
    o4[1] = make_float4(pv[4] * inv, pv[5] * inv, pv[6] * inv, pv[7] * inv);
}

/* ------------------------------------------------------------------ */
/* 3. fused post-block: LN2(LN1(x+proj) + ff); optional next-layer qkv */
/* ------------------------------------------------------------------ */
__global__ void __launch_bounds__(128) k_post(int layer, int do_qkv,
        const float* __restrict__ encob,
        const float* __restrict__ ln1g, const float* __restrict__ ln1b,
        const float* __restrict__ ff1b, const float* __restrict__ ff2b,
        const float* __restrict__ ln2g, const float* __restrict__ ln2b,
        const float* __restrict__ encinb) {
    __shared__ __align__(16) float sWo[1024];
    __shared__ __align__(16) float sW1[2048];
    __shared__ __align__(16) float sW2[2048];
    __shared__ __align__(16) float sWq[3072];
    __shared__ float sbo[32], sl1g[32], sl1b[32], sb1[64], sb2[32],
                     sl2g[32], sl2b[32], sbq[96];
    int t = threadIdx.x;
    for (int i = t; i < 1024; i += 128) sWo[i] = gWt_out[layer * 1024 + i];
    for (int i = t; i < 2048; i += 128) sW1[i] = gWt_ff1[layer * 2048 + i];
    for (int i = t; i < 2048; i += 128) sW2[i] = gWt_ff2[layer * 2048 + i];
    if (do_qkv) for (int i = t; i < 3072; i += 128) sWq[i] = gWt_qkv[3072 + i];
    if (t < 32) {
        sbo[t] = encob[layer * 32 + t];
        sl1g[t] = ln1g[layer * 32 + t]; sl1b[t] = ln1b[layer * 32 + t];
        sb2[t] = ff2b[layer * 32 + t];
        sl2g[t] = ln2g[layer * 32 + t]; sl2b[t] = ln2b[layer * 32 + t];
    }
    if (t < 64) sb1[t] = ff1b[layer * 64 + t];
    if (do_qkv && t < 96) sbq[t] = encinb[96 + t];
    __syncthreads();
    int token = blockIdx.x * 128 + t;

    float a[32];
    {
        const float4* ar = (const float4*)(g_ao + (size_t)token * 32);
#pragma unroll
        for (int i = 0; i < 8; i++) {
            float4 v = ar[i];
            a[i * 4] = v.x; a[i * 4 + 1] = v.y; a[i * 4 + 2] = v.z; a[i * 4 + 3] = v.w;
        }
    }
    u64 racc[16];
#pragma unroll
    for (int p = 0; p < 16; p++) racc[p] = pk2(sbo[2 * p], sbo[2 * p + 1]);
#pragma unroll 4
    for (int k = 0; k < 32; k++) mat32_f32x2(racc, a[k], sWo + k * 32);
    float r[32];
#pragma unroll
    for (int p = 0; p < 16; p++) {
        float2 v = unpk(racc[p]);
        r[2 * p] = v.x; r[2 * p + 1] = v.y;
    }
    {
        const float4* xr = (const float4*)(g_x + (size_t)token * 32);
#pragma unroll
        for (int i = 0; i < 8; i++) {
            float4 v = xr[i];
            r[i * 4] += v.x; r[i * 4 + 1] += v.y; r[i * 4 + 2] += v.z; r[i * 4 + 3] += v.w;
        }
    }
    float mu = 0.f;
#pragma unroll
    for (int c = 0; c < 32; c++) mu += r[c];
    mu *= (1.f / 32.f);
    float var = 0.f;
#pragma unroll
    for (int c = 0; c < 32; c++) { float d = r[c] - mu; var += d * d; }
    var *= (1.f / 32.f);
    float isd = sqrtf(var + 1e-5f);
#pragma unroll
    for (int c = 0; c < 32; c++) r[c] = sl1g[c] * (r[c] - mu) / isd + sl1b[c];

    u64 oacc[16];
#pragma unroll
    for (int p = 0; p < 16; p++) oacc[p] = pk2(sb2[2 * p], sb2[2 * p + 1]);
#pragma unroll
    for (int half = 0; half < 2; half++) {
        u64 hacc[16];
#pragma unroll
        for (int p = 0; p < 16; p++)
            hacc[p] = pk2(sb1[half * 32 + 2 * p], sb1[half * 32 + 2 * p + 1]);
#pragma unroll 4
        for (int k = 0; k < 32; k++)
            mat32_f32x2(hacc, r[k], sW1 + k * 64 + half * 32);
        float h[32];
#pragma unroll
        for (int p = 0; p < 16; p++) {
            float2 v = unpk(hacc[p]);
            h[2 * p] = fmaxf(v.x, 0.f); h[2 * p + 1] = fmaxf(v.y, 0.f);
        }
#pragma unroll 4
        for (int k = 0; k < 32; k++)
            mat32_f32x2(oacc, h[k], sW2 + (half * 32 + k) * 32);
    }
#pragma unroll
    for (int p = 0; p < 16; p++) {
        float2 v = unpk(oacc[p]);
        r[2 * p] += v.x; r[2 * p + 1] += v.y;
    }
    mu = 0.f;
#pragma unroll
    for (int c = 0; c < 32; c++) mu += r[c];
    mu *= (1.f / 32.f);
    var = 0.f;
#pragma unroll
    for (int c = 0; c < 32; c++) { float d = r[c] - mu; var += d * d; }
    var *= (1.f / 32.f);
    isd = sqrtf(var + 1e-5f);
#pragma unroll
    for (int c = 0; c < 32; c++) r[c] = sl2g[c] * (r[c] - mu) / isd + sl2b[c];

    float4* xo = (float4*)(g_x + (size_t)token * 32);
#pragma unroll
    for (int c4 = 0; c4 < 8; c4++)
        xo[c4] = make_float4(r[c4 * 4], r[c4 * 4 + 1], r[c4 * 4 + 2], r[c4 * 4 + 3]);

    if (do_qkv)
        qkv_from_x(r, sWq, sbq, g_qkv + (size_t)token * 96);
}

/* ------------------------------------------------------------------ */
/* 4. xc_out = x[:, :16] @ fc_out_w^T + b ; plus |row|^2               */
/* ------------------------------------------------------------------ */
__global__ void __launch_bounds__(256) k_fcout(const float* __restrict__ W,
                                               const float* __restrict__ b) {
    __shared__ float xs[DM];
    __shared__ float red[256];
    int n = blockIdx.x;
    int t = (n >> 4) * SEQ + (n & 15);
    if (threadIdx.x < DM) xs[threadIdx.x] = g_x[t * DM + threadIdx.x];
    __syncthreads();
    float sq = 0.f;
#pragma unroll
    for (int r = 0; r < 3; r++) {
        int j = threadIdx.x + 256 * r;
        float acc = b[j];
#pragma unroll
        for (int c = 0; c < 32; c++) acc += xs[c] * W[j * DM + c];
        g_xc[(size_t)n * EMBD + j] = acc;
        sq += acc * acc;
    }
    red[threadIdx.x] = sq;
    __syncthreads();
    for (int o = 128; o; o >>= 1) {
        if (threadIdx.x < o) red[threadIdx.x] += red[threadIdx.x + o];
        __syncthreads();
    }
    if (threadIdx.x == 0) g_xn2[n] = red[0];
}

/* ------------------------------------------------------------------ */
/* 5. codebook row norms                                               */
/* ------------------------------------------------------------------ */
__global__ void __launch_bounds__(256) k_cn2(const float* __restrict__ cb) {
    int warp = threadIdx.x >> 5, lane = threadIdx.x & 31;
    int c = blockIdx.x * 8 + warp;
    const float* r = cb + (size_t)c * EMBD;
    float s = 0.f;
    for (int i = lane; i < EMBD; i += 32) { float v = r[i]; s += v * v; }
#pragma unroll
    for (int o = 16; o; o >>= 1) s += __shfl_xor_sync(0xffffffffu, s, o);
    if (lane == 0) g_cn2[c] = s;
}

/* ------------------------------------------------------------------ */
/* 6. logits GEMM: 128x128 tile, 8x8/thread, f32x2 packed FMA          */
/* ------------------------------------------------------------------ */
__global__ void __launch_bounds__(256) k_gemm(const float* __restrict__ cb) {
    __shared__ __align__(16) float As[16][264];   /* duplicated pairs */
    __shared__ __align__(16) float Bs[16][132];
    int bm = blockIdx.y * 128, bn = blockIdx.x * 128;
    int tid = threadIdx.x;
    int tx = tid & 15, ty = tid >> 4;
    u64 acc2[8][4];
#pragma unroll
    for (int i = 0; i < 8; i++)
#pragma unroll
        for (int j = 0; j < 4; j++) acc2[i][j] = 0ull;

    int lm = tid >> 1, lk = (tid & 1) * 8;
    for (int k0 = 0; k0 < 768; k0 += 16) {
        {
            const float4* sa = (const float4*)(g_xc + (size_t)(bm + lm) * 768 + k0 + lk);
            float4 v0 = sa[0], v1 = sa[1];
            *(u64*)&As[lk + 0][2 * lm] = dup2(v0.x);
            *(u64*)&As[lk + 1][2 * lm] = dup2(v0.y);
            *(u64*)&As[lk + 2][2 * lm] = dup2(v0.z);
            *(u64*)&As[lk + 3][2 * lm] = dup2(v0.w);
            *(u64*)&As[lk + 4][2 * lm] = dup2(v1.x);
            *(u64*)&As[lk + 5][2 * lm] = dup2(v1.y);
            *(u64*)&As[lk + 6][2 * lm] = dup2(v1.z);
            *(u64*)&As[lk + 7][2 * lm] = dup2(v1.w);
            const float4* sb = (const float4*)(cb + (size_t)(bn + lm) * 768 + k0 + lk);
            float4 w0 = sb[0], w1 = sb[1];
            Bs[lk + 0][lm] = w0.x; Bs[lk + 1][lm] = w0.y; Bs[lk + 2][lm] = w0.z; Bs[lk + 3][lm] = w0.w;
            Bs[lk + 4][lm] = w1.x; Bs[lk + 5][lm] = w1.y; Bs[lk + 6][lm] = w1.z; Bs[lk + 7][lm] = w1.w;
        }
        __syncthreads();
#pragma unroll
        for (int kk = 0; kk < 16; kk++) {
            const u64* Ad = (const u64*)&As[kk][0];
            u64 av2[8];
#pragma unroll
            for (int i = 0; i < 4; i++) av2[i] = Ad[ty * 4 + i];
#pragma unroll
            for (int i = 0; i < 4; i++) av2[4 + i] = Ad[64 + ty * 4 + i];
            ulonglong2 q0 = *(const ulonglong2*)&Bs[kk][tx * 4];
            ulonglong2 q1 = *(const ulonglong2*)&Bs[kk][64 + tx * 4];
#pragma unroll
            for (int i = 0; i < 8; i++) {
                fma2(acc2[i][0], av2[i], q0.x);
                fma2(acc2[i][1], av2[i], q0.y);
                fma2(acc2[i][2], av2[i], q1.x);
                fma2(acc2[i][3], av2[i], q1.y);
            }
        }
        __syncthreads();
    }
    int rows[8];
#pragma unroll
    for (int i = 0; i < 4; i++) { rows[i] = bm + ty * 4 + i; rows[4 + i] = bm + 64 + ty * 4 + i; }
    int c0 = bn + tx * 4, c1 = bn + 64 + tx * 4;
    float cn[8];
#pragma unroll
    for (int j = 0; j < 4; j++) { cn[j] = g_cn2[c0 + j]; cn[4 + j] = g_cn2[c1 + j]; }
#pragma unroll
    for (int i = 0; i < 8; i++) {
        float xn = g_xn2[rows[i]];
        float* rowp = g_logit + (size_t)rows[i] * NCODES;
        float2 p0 = unpk(acc2[i][0]), p1 = unpk(acc2[i][1]);
        float2 p2 = unpk(acc2[i][2]), p3 = unpk(acc2[i][3]);
        float4 s0, s1;
        s0.x = -(xn + cn[0] - 2.f * p0.x) - 1e-5f;
        s0.y = -(xn + cn[1] - 2.f * p0.y) - 1e-5f;
        s0.z = -(xn + cn[2] - 2.f * p1.x) - 1e-5f;
        s0.w = -(xn + cn[3] - 2.f * p1.y) - 1e-5f;
        s1.x = -(xn + cn[4] - 2.f * p2.x) - 1e-5f;
        s1.y = -(xn + cn[5] - 2.f * p2.y) - 1e-5f;
        s1.z = -(xn + cn[6] - 2.f * p3.x) - 1e-5f;
        s1.w = -(xn + cn[7] - 2.f * p3.y) - 1e-5f;
        *(float4*)(rowp + c0) = s0;
        *(float4*)(rowp + c1) = s1;
    }
}

/* ------------------------------------------------------------------ */
/* 7. fused rowmax + candidates (gumbel span 20.413)                   */
/* ------------------------------------------------------------------ */
__global__ void __launch_bounds__(256) k_cand() {
    __shared__ float red[256];
    __shared__ float s_thr;
    __shared__ int   s_cnt;
    int n = blockIdx.x;
    const float* row = g_logit + (size_t)n * NCODES;
    float m = -3.0e38f;
    for (int k = threadIdx.x; k < NCODES; k += 256) m = fmaxf(m, row[k]);
    red[threadIdx.x] = m;
    __syncthreads();
    for (int o = 128; o; o >>= 1) {
        if (threadIdx.x < o) red[threadIdx.x] = fmaxf(red[threadIdx.x], red[threadIdx.x + o]);
        __syncthreads();
    }
    if (threadIdx.x == 0) { s_thr = red[0] - 20.45f; s_cnt = 0; }
    __syncthreads();
    float thr = s_thr;
    for (int k = threadIdx.x; k < NCODES; k += 256) {
        if (row[k] >= thr) {
            int p = atomicAdd(&s_cnt, 1);
            if (p < 64) g_cand[(size_t)n * 64 + p] = k;
        }
    }
    __syncthreads();
    if (threadIdx.x == 0) { g_candcnt[n] = s_cnt; g_thr[n] = thr; }
}

/* ------------------------------------------------------------------ */
/* 8. exact jax categorical (partitionable threefry)                   */
/* ------------------------------------------------------------------ */
__global__ void __launch_bounds__(512) k_sample() {
    int n = blockIdx.x;
    int s = threadIdx.x >> 5, lane = threadIdx.x & 31;
    int cnt = g_candcnt[n];
    const float* row = g_logit + (size_t)n * NCODES;
    uint32_t base = ((uint32_t)s << 23) | ((uint32_t)n << 13);
    float v = -3.0e38f;
    int best = 0x7fffffff;
    if (cnt <= 64) {
        const int* cl = g_cand + (size_t)n * 64;
        for (int ci = lane; ci < cnt; ci += 32) {
            int k = cl[ci];
            float val = row[k] + gumbel_idx(base | (uint32_t)k);
            if (val > v || (val == v && k < best)) { v = val; best = k; }
        }
    } else {
        float thr = g_thr[n];
        for (int k = lane; k < NCODES; k += 32) {
            float lg = row[k];
            if (lg >= thr) {
                float val = lg + gumbel_idx(base | (uint32_t)k);
                if (val > v || (val == v && k < best)) { v = val; best = k; }
            }
        }
    }
#pragma unroll
    for (int o = 16; o; o >>= 1) {
        float tv = __shfl_down_sync(0xffffffffu, v, o);
        int   tk = __shfl_down_sync(0xffffffffu, best, o);
        if (tv > v || (tv == v && tk < best)) { v = tv; best = tk; }
    }
    if (lane == 0) g_draw[s * NROWS + n] = best;
}

/* ------------------------------------------------------------------ */
/* 9. output: xc_out + (mean(cb[draws]) - xc_out)                      */
/* ------------------------------------------------------------------ */
__global__ void __launch_bounds__(256) k_out(const float* __restrict__ cb,
                                             float* __restrict__ out) {
    __shared__ int dr[16];
    int n = blockIdx.x;
    if (threadIdx.x < 16) dr[threadIdx.x] = g_draw[threadIdx.x * NROWS + n];
    __syncthreads();
#pragma unroll
    for (int r = 0; r < 3; r++) {
        int j = threadIdx.x + 256 * r;
        float q = 0.f;
#pragma unroll
        for (int s = 0; s < 16; s++) q += cb[(size_t)dr[s] * EMBD + j];
        float xc = g_xc[(size_t)n * EMBD + j];
        out[(size_t)n * EMBD + j] = xc + (q * 0.0625f - xc);
    }
}

/* ------------------------------------------------------------------ */
extern "C" void kernel_launch(void* const* d_in, const int* in_sizes, int n_in,
                              void* d_out, int out_size) {
    const float* xcq      = (const float*)d_in[0];
    const int*   amask    = (const int*)  d_in[1];
    const float* fc_in_w  = (const float*)d_in[2];
    const float* fc_in_b  = (const float*)d_in[3];
    const float* fc_out_w = (const float*)d_in[4];
    const float* fc_out_b = (const float*)d_in[5];
    const float* enc_in_w = (const float*)d_in[6];
    const float* enc_in_b = (const float*)d_in[7];
    const float* enc_ow   = (const float*)d_in[8];
    const float* enc_ob   = (const float*)d_in[9];
    const float* ff1_w    = (const float*)d_in[10];
    const float* ff1_b    = (const float*)d_in[11];
    const float* ff2_w    = (const float*)d_in[12];
    const float* ff2_b    = (const float*)d_in[13];
    const float* ln1_g    = (const float*)d_in[14];
    const float* ln1_b    = (const float*)d_in[15];
    const float* ln2_g    = (const float*)d_in[16];
    const float* ln2_b    = (const float*)d_in[17];
    const float* cb       = (const float*)d_in[18];
    float* out = (float*)d_out;

    k_prep<<<160, 256>>>(fc_in_w, enc_in_w, enc_ow, ff1_w, ff2_w);
    k_cn2<<<NCODES / 8, 256>>>(cb);
    k_fcin<<<NTOK / 128, 128>>>(xcq, fc_in_b, enc_in_b);
    k_attn<<<BATCH * NH, 512>>>(amask);
    k_post<<<NTOK / 128, 128>>>(0, 1, enc_ob, ln1_g, ln1_b, ff1_b, ff2_b,
                                ln2_g, ln2_b, enc_in_b);
    k_attn<<<BATCH * NH, 512>>>(amask);
    k_post<<<NTOK / 128, 128>>>(1, 0, enc_ob, ln1_g, ln1_b, ff1_b, ff2_b,
                                ln2_g, ln2_b, enc_in_b);
    k_fcout<<<NROWS, 256>>>(fc_out_w, fc_out_b);
    k_gemm<<<dim3(NCODES / 128, NROWS / 128), 256>>>(cb);
    k_cand<<<NROWS, 256>>>();
    k_sample<<<NROWS, 512>>>();
    k_out<<<NROWS, 256>>>(cb, out);

    /* second tuple element: passthrough copy of xcq */
    cudaMemcpyAsync(out + (size_t)NROWS * EMBD, xcq,
                    (size_t)NTOK * EMBD * sizeof(float),
                    cudaMemcpyDeviceToDevice);
}